// round 1
// baseline (speedup 1.0000x reference)
#include <cuda_runtime.h>
#include <math.h>

#define NB   8192
#define ND   1024
#define BM   128
#define BN   128
#define BK   16
#define NSPLIT 4
#define COLTILES (NB / BN)                 /* 64 */
#define TILES_PER_SPLIT (COLTILES / NSPLIT) /* 16 */

// Scratch (static device globals — no allocation)
__device__ float  g_xn[NB * ND];          // normalized rows, 32 MB
__device__ float2 g_part[NB * NSPLIT];    // per-split top-2 dots per row

// ---------------------------------------------------------------------------
// Kernel 1: row L2-normalize. One block (256 threads) per row, float4 I/O.
// ---------------------------------------------------------------------------
__global__ void __launch_bounds__(256) normalize_kernel(const float* __restrict__ x) {
    int row = blockIdx.x;
    int t = threadIdx.x;
    const float4* xr = reinterpret_cast<const float4*>(x + (size_t)row * ND);
    float4* xo = reinterpret_cast<float4*>(g_xn + (size_t)row * ND);

    float4 v = xr[t];  // 256 threads * 4 = 1024 elements exactly
    float s = v.x * v.x + v.y * v.y + v.z * v.z + v.w * v.w;

    #pragma unroll
    for (int o = 16; o > 0; o >>= 1) s += __shfl_xor_sync(0xFFFFFFFFu, s, o);

    __shared__ float ws[8];
    int lane = t & 31, w = t >> 5;
    if (lane == 0) ws[w] = s;
    __syncthreads();
    if (t < 8) {
        float q = ws[t];
        #pragma unroll
        for (int o = 4; o > 0; o >>= 1) q += __shfl_xor_sync(0x000000FFu, q, o);
        if (t == 0) ws[0] = q;
    }
    __syncthreads();

    float inv = 1.0f / fmaxf(sqrtf(ws[0]), 1e-8f);
    v.x *= inv; v.y *= inv; v.z *= inv; v.w *= inv;
    xo[t] = v;
}

// ---------------------------------------------------------------------------
// Kernel 2: tiled fp32 "GEMM" with running top-2 per row (diag masked).
// Grid: (64 row tiles, NSPLIT column splits). 256 threads, 8x8 per thread.
// ---------------------------------------------------------------------------
__global__ void __launch_bounds__(256) top2_kernel() {
    __shared__ float  As[BK][BM];
    __shared__ float  Bs[BK][BN];
    __shared__ float2 s_red[BM][16];   // per-column-group partial top-2

    const int rowStart = blockIdx.x * BM;
    const int split    = blockIdx.y;
    const int tid = threadIdx.x;
    const int tx = tid & 15;        // column group 0..15
    const int ty = tid >> 4;        // row group 0..15

    // running top-2 for row (rowStart + tid), held by threads tid < 128
    float2 run = make_float2(-2.0f, -2.0f);

    for (int ct = 0; ct < TILES_PER_SPLIT; ct++) {
        const int colStart = (split * TILES_PER_SPLIT + ct) * BN;

        float acc[8][8];
        #pragma unroll
        for (int i = 0; i < 8; i++)
            #pragma unroll
            for (int j = 0; j < 8; j++) acc[i][j] = 0.0f;

        for (int k0 = 0; k0 < ND; k0 += BK) {
            // Load tiles (transposed to [BK][128]); 2 float4 per thread per matrix.
            #pragma unroll
            for (int l = 0; l < 2; l++) {
                int idx = tid * 2 + l;        // 0..511
                int r   = idx >> 2;           // 0..127
                int c4  = idx & 3;            // 0..3 (group of 4 k's)
                float4 va = *reinterpret_cast<const float4*>(
                    g_xn + (size_t)(rowStart + r) * ND + k0 + c4 * 4);
                As[c4 * 4 + 0][r] = va.x;
                As[c4 * 4 + 1][r] = va.y;
                As[c4 * 4 + 2][r] = va.z;
                As[c4 * 4 + 3][r] = va.w;
                float4 vb = *reinterpret_cast<const float4*>(
                    g_xn + (size_t)(colStart + r) * ND + k0 + c4 * 4);
                Bs[c4 * 4 + 0][r] = vb.x;
                Bs[c4 * 4 + 1][r] = vb.y;
                Bs[c4 * 4 + 2][r] = vb.z;
                Bs[c4 * 4 + 3][r] = vb.w;
            }
            __syncthreads();

            #pragma unroll
            for (int k = 0; k < BK; k++) {
                float4 a0 = *reinterpret_cast<const float4*>(&As[k][ty * 8]);
                float4 a1 = *reinterpret_cast<const float4*>(&As[k][ty * 8 + 4]);
                float4 b0 = *reinterpret_cast<const float4*>(&Bs[k][tx * 8]);
                float4 b1 = *reinterpret_cast<const float4*>(&Bs[k][tx * 8 + 4]);
                float ra[8] = {a0.x, a0.y, a0.z, a0.w, a1.x, a1.y, a1.z, a1.w};
                float rb[8] = {b0.x, b0.y, b0.z, b0.w, b1.x, b1.y, b1.z, b1.w};
                #pragma unroll
                for (int i = 0; i < 8; i++)
                    #pragma unroll
                    for (int j = 0; j < 8; j++)
                        acc[i][j] = fmaf(ra[i], rb[j], acc[i][j]);
            }
            __syncthreads();
        }

        // Per-thread top-2 over its 8 columns, per row; mask diagonal.
        #pragma unroll
        for (int i = 0; i < 8; i++) {
            int r = rowStart + ty * 8 + i;
            float a1 = -2.0f, a2 = -2.0f;
            #pragma unroll
            for (int j = 0; j < 8; j++) {
                int c = colStart + tx * 8 + j;
                float v = (c == r) ? -2.0f : acc[i][j];
                if (v > a1) { a2 = a1; a1 = v; }
                else if (v > a2) { a2 = v; }
            }
            s_red[ty * 8 + i][tx] = make_float2(a1, a2);
        }
        __syncthreads();

        if (tid < BM) {
            float2 t = run;
            #pragma unroll
            for (int p = 0; p < 16; p++) {
                float2 q = s_red[tid][p];
                if (q.x > t.x) { t.y = fmaxf(t.x, q.y); t.x = q.x; }
                else           { t.y = fmaxf(t.y, q.x); }
            }
            run = t;
        }
        __syncthreads();   // protect s_red before next iteration overwrites it
    }

    if (tid < BM) g_part[(size_t)(rowStart + tid) * NSPLIT + split] = run;
}

// ---------------------------------------------------------------------------
// Kernel 3: merge splits, compute losses/gates, final scalar.
// ---------------------------------------------------------------------------
__global__ void __launch_bounds__(256) loss_kernel(float* __restrict__ out) {
    const int t = threadIdx.x;
    float sum_lg = 0.0f, sum_g = 0.0f;

    for (int r = t; r < NB; r += 256) {
        float2 m = g_part[(size_t)r * NSPLIT + 0];
        #pragma unroll
        for (int p = 1; p < NSPLIT; p++) {
            float2 q = g_part[(size_t)r * NSPLIT + p];
            if (q.x > m.x) { m.y = fmaxf(m.x, q.y); m.x = q.x; }
            else           { m.y = fmaxf(m.y, q.x); }
        }
        float d2[2] = {m.x, m.y};
        #pragma unroll
        for (int e = 0; e < 2; e++) {
            float dist = sqrtf(fmaxf(2.0f - 2.0f * d2[e], 0.0f));
            float loss = -logf(dist + 1e-8f);
            float g    = 1.0f / (1.0f + expf(-(loss - 0.5f) * 10.0f));
            sum_lg += loss * g;
            sum_g  += g;
        }
    }

    // block reduce two sums
    #pragma unroll
    for (int o = 16; o > 0; o >>= 1) {
        sum_lg += __shfl_xor_sync(0xFFFFFFFFu, sum_lg, o);
        sum_g  += __shfl_xor_sync(0xFFFFFFFFu, sum_g,  o);
    }
    __shared__ float s_lg[8], s_g[8];
    int lane = t & 31, w = t >> 5;
    if (lane == 0) { s_lg[w] = sum_lg; s_g[w] = sum_g; }
    __syncthreads();
    if (t == 0) {
        float tl = 0.0f, tg = 0.0f;
        #pragma unroll
        for (int i = 0; i < 8; i++) { tl += s_lg[i]; tg += s_g[i]; }
        float weighted_mean = tl / (float)(NB * 2);
        float gated_mean    = tl / fmaxf(tg, 1.0f);
        out[0] = 0.5f * weighted_mean + 0.5f * gated_mean;
    }
}

// ---------------------------------------------------------------------------
extern "C" void kernel_launch(void* const* d_in, const int* in_sizes, int n_in,
                              void* d_out, int out_size) {
    const float* x = (const float*)d_in[0];
    float* out = (float*)d_out;

    normalize_kernel<<<NB, 256>>>(x);
    dim3 grid(COLTILES, NSPLIT);
    top2_kernel<<<grid, 256>>>();
    loss_kernel<<<1, 256>>>(out);
}

// round 3
// speedup vs baseline: 6.4641x; 6.4641x over previous
#include <cuda_runtime.h>
#include <cuda_fp16.h>
#include <cstdint>
#include <math.h>

#define NB 8192
#define ND 1024
#define BM 128
#define BN 128
#define BK 32
#define NSPLIT 8
#define COLTILES (NB / BN)            /* 64 */
#define TPS (COLTILES / NSPLIT)       /* 8 col tiles per CTA */
#define THREADS 256
#define LDS_PAD 40                    /* halves per smem row (80B stride) */
#define KBLOCKS (ND / BK)             /* 32 */

// ---------------- static device scratch (no allocation) --------------------
__device__ __half g_h[NB * ND];            // normalized rows in fp16 (16 MB)
__device__ float2 g_part[NB * NSPLIT];     // per-split top-2 per row

// ---------------- PTX helpers ----------------------------------------------
__device__ __forceinline__ uint32_t smem_u32(const void* p) {
    uint32_t a;
    asm("{ .reg .u64 t; cvta.to.shared.u64 t, %1; cvt.u32.u64 %0, t; }" : "=r"(a) : "l"(p));
    return a;
}
#define CP_ASYNC16(sm, gp) \
    asm volatile("cp.async.cg.shared.global [%0], [%1], 16;" :: "r"(sm), "l"(gp))
#define CP_COMMIT() asm volatile("cp.async.commit_group;" ::: "memory")
#define CP_WAIT1()  asm volatile("cp.async.wait_group 1;" ::: "memory")
#define CP_WAIT0()  asm volatile("cp.async.wait_group 0;" ::: "memory")
#define LDMATRIX_X4(r0, r1, r2, r3, addr) \
    asm volatile("ldmatrix.sync.aligned.m8n8.x4.shared.b16 {%0,%1,%2,%3}, [%4];" \
                 : "=r"(r0), "=r"(r1), "=r"(r2), "=r"(r3) : "r"(addr))
#define MMA16816(c, a, b0, b1) \
    asm volatile("mma.sync.aligned.m16n8k16.row.col.f32.f16.f16.f32 " \
                 "{%0,%1,%2,%3},{%4,%5,%6,%7},{%8,%9},{%0,%1,%2,%3};" \
                 : "+f"((c)[0]), "+f"((c)[1]), "+f"((c)[2]), "+f"((c)[3]) \
                 : "r"((a)[0]), "r"((a)[1]), "r"((a)[2]), "r"((a)[3]), "r"(b0), "r"(b1))

__device__ __forceinline__ void top2_merge(float2& t, float2 q) {
    if (q.x > t.x) { t.y = fmaxf(t.x, q.y); t.x = q.x; }
    else           { t.y = fmaxf(t.y, q.x); }
}
__device__ __forceinline__ void top2_push(float2& t, float v) {
    if (v > t.x) { t.y = t.x; t.x = v; }
    else if (v > t.y) { t.y = v; }
}

// ---------------------------------------------------------------------------
// Kernel 1: L2-normalize rows, store fp16
// ---------------------------------------------------------------------------
__global__ void __launch_bounds__(256) normalize_kernel(const float* __restrict__ x) {
    int row = blockIdx.x;
    int t = threadIdx.x;
    const float4* xr = reinterpret_cast<const float4*>(x + (size_t)row * ND);
    float4 v = xr[t];
    float s = v.x * v.x + v.y * v.y + v.z * v.z + v.w * v.w;
    #pragma unroll
    for (int o = 16; o > 0; o >>= 1) s += __shfl_xor_sync(0xFFFFFFFFu, s, o);
    __shared__ float ws[8];
    int lane = t & 31, w = t >> 5;
    if (lane == 0) ws[w] = s;
    __syncthreads();
    if (t < 8) {
        float q = ws[t];
        #pragma unroll
        for (int o = 4; o > 0; o >>= 1) q += __shfl_xor_sync(0x000000FFu, q, o);
        if (t == 0) ws[0] = q;
    }
    __syncthreads();
    float inv = 1.0f / fmaxf(sqrtf(ws[0]), 1e-8f);
    __half2* oh = reinterpret_cast<__half2*>(g_h + (size_t)row * ND);
    oh[t * 2 + 0] = __floats2half2_rn(v.x * inv, v.y * inv);
    oh[t * 2 + 1] = __floats2half2_rn(v.z * inv, v.w * inv);
}

// ---------------------------------------------------------------------------
// Kernel 2: fp16 mma.sync 128x128 tiles with running per-row top-2
// ---------------------------------------------------------------------------
__global__ void __launch_bounds__(THREADS) top2_mma_kernel() {
    __shared__ __half sA[2][BM * LDS_PAD];
    __shared__ __half sB[2][BN * LDS_PAD];
    __shared__ float2 s_red[4][BM];

    const int tid = threadIdx.x;
    const int wid = tid >> 5, lane = tid & 31;
    const int warpM = wid >> 2, warpN = wid & 3;   // 2 x 4 warp grid
    const int rowStart = blockIdx.x * BM;
    const int split = blockIdx.y;

    const uint32_t sAu = smem_u32(&sA[0][0]);
    const uint32_t sBu = smem_u32(&sB[0][0]);
    const uint32_t BUFB = BM * LDS_PAD * 2;        // bytes per buffer

    // ldmatrix lane address components
    const int a_r = lane & 15;                     // row within 16-row tile
    const int a_k = (lane >> 4) << 3;              // 0 or 8 (k offset)
    const int b_n = (lane & 7) + ((lane >> 4) << 3);
    const int b_k = ((lane >> 3) & 1) << 3;

    // load-chunk decomposition: chunk c -> row c>>2, 16B k-chunk c&3
    const int l_r0 = tid >> 2, l_k0 = tid & 3;
    const int l_r1 = (tid + 256) >> 2, l_k1 = (tid + 256) & 3;

    // running top-2 for this thread's 8 rows: index = mi*2 + half
    float2 run[8];
    #pragma unroll
    for (int i = 0; i < 8; i++) run[i] = make_float2(-2.0f, -2.0f);

    for (int ct = 0; ct < TPS; ct++) {
        const int colStart = (split * TPS + ct) * BN;

        float acc[4][4][4];
        #pragma unroll
        for (int mi = 0; mi < 4; mi++)
            #pragma unroll
            for (int nj = 0; nj < 4; nj++)
                #pragma unroll
                for (int e = 0; e < 4; e++) acc[mi][nj][e] = 0.0f;

        // ---- prologue: stage 0 ----
        {
            const int k0 = 0;
            CP_ASYNC16(sAu + (l_r0 * LDS_PAD + l_k0 * 8) * 2,
                       g_h + (size_t)(rowStart + l_r0) * ND + k0 + l_k0 * 8);
            CP_ASYNC16(sAu + (l_r1 * LDS_PAD + l_k1 * 8) * 2,
                       g_h + (size_t)(rowStart + l_r1) * ND + k0 + l_k1 * 8);
            CP_ASYNC16(sBu + (l_r0 * LDS_PAD + l_k0 * 8) * 2,
                       g_h + (size_t)(colStart + l_r0) * ND + k0 + l_k0 * 8);
            CP_ASYNC16(sBu + (l_r1 * LDS_PAD + l_k1 * 8) * 2,
                       g_h + (size_t)(colStart + l_r1) * ND + k0 + l_k1 * 8);
            CP_COMMIT();
        }

        for (int kb = 0; kb < KBLOCKS; kb++) {
            if (kb + 1 < KBLOCKS) {
                const int k0 = (kb + 1) * BK;
                const uint32_t bo = ((kb + 1) & 1) * BUFB;
                CP_ASYNC16(sAu + bo + (l_r0 * LDS_PAD + l_k0 * 8) * 2,
                           g_h + (size_t)(rowStart + l_r0) * ND + k0 + l_k0 * 8);
                CP_ASYNC16(sAu + bo + (l_r1 * LDS_PAD + l_k1 * 8) * 2,
                           g_h + (size_t)(rowStart + l_r1) * ND + k0 + l_k1 * 8);
                CP_ASYNC16(sBu + bo + (l_r0 * LDS_PAD + l_k0 * 8) * 2,
                           g_h + (size_t)(colStart + l_r0) * ND + k0 + l_k0 * 8);
                CP_ASYNC16(sBu + bo + (l_r1 * LDS_PAD + l_k1 * 8) * 2,
                           g_h + (size_t)(colStart + l_r1) * ND + k0 + l_k1 * 8);
                CP_COMMIT();
                CP_WAIT1();
            } else {
                CP_WAIT0();
            }
            __syncthreads();

            const uint32_t bo = (kb & 1) * BUFB;
            #pragma unroll
            for (int ks = 0; ks < 2; ks++) {
                uint32_t af[4][4];
                #pragma unroll
                for (int mi = 0; mi < 4; mi++) {
                    uint32_t addr = sAu + bo +
                        ((warpM * 64 + mi * 16 + a_r) * LDS_PAD + ks * 16 + a_k) * 2;
                    LDMATRIX_X4(af[mi][0], af[mi][1], af[mi][2], af[mi][3], addr);
                }
                uint32_t bf[2][4];
                #pragma unroll
                for (int nb = 0; nb < 2; nb++) {
                    uint32_t addr = sBu + bo +
                        ((warpN * 32 + nb * 16 + b_n) * LDS_PAD + ks * 16 + b_k) * 2;
                    LDMATRIX_X4(bf[nb][0], bf[nb][1], bf[nb][2], bf[nb][3], addr);
                }
                #pragma unroll
                for (int mi = 0; mi < 4; mi++)
                    #pragma unroll
                    for (int nj = 0; nj < 4; nj++)
                        MMA16816(acc[mi][nj], af[mi],
                                 bf[nj >> 1][(nj & 1) * 2], bf[nj >> 1][(nj & 1) * 2 + 1]);
            }
            __syncthreads();
        }

        // ---- fold this tile into running top-2 (mask diagonal) ----
        #pragma unroll
        for (int mi = 0; mi < 4; mi++) {
            const int row0 = rowStart + warpM * 64 + mi * 16 + (lane >> 2);
            #pragma unroll
            for (int nj = 0; nj < 4; nj++) {
                const int col0 = colStart + warpN * 32 + nj * 8 + (lane & 3) * 2;
                float c0 = acc[mi][nj][0], c1 = acc[mi][nj][1];
                float c2 = acc[mi][nj][2], c3 = acc[mi][nj][3];
                if (col0     == row0)     c0 = -2.0f;
                if (col0 + 1 == row0)     c1 = -2.0f;
                if (col0     == row0 + 8) c2 = -2.0f;
                if (col0 + 1 == row0 + 8) c3 = -2.0f;
                top2_push(run[mi * 2 + 0], c0);
                top2_push(run[mi * 2 + 0], c1);
                top2_push(run[mi * 2 + 1], c2);
                top2_push(run[mi * 2 + 1], c3);
            }
        }
    }

    // ---- reduce across lane quads (same rows live in lanes with equal lane>>2) ----
    #pragma unroll
    for (int i = 0; i < 8; i++) {
        #pragma unroll
        for (int o = 1; o <= 2; o <<= 1) {
            float2 q;
            q.x = __shfl_xor_sync(0xFFFFFFFFu, run[i].x, o);
            q.y = __shfl_xor_sync(0xFFFFFFFFu, run[i].y, o);
            top2_merge(run[i], q);
        }
    }
    if ((lane & 3) == 0) {
        #pragma unroll
        for (int mi = 0; mi < 4; mi++) {
            int rbase = warpM * 64 + mi * 16 + (lane >> 2);
            s_red[warpN][rbase]     = run[mi * 2 + 0];
            s_red[warpN][rbase + 8] = run[mi * 2 + 1];
        }
    }
    __syncthreads();

    // ---- merge the 4 N-warps, emit per-split result ----
    if (tid < BM) {
        float2 m = s_red[0][tid];
        top2_merge(m, s_red[1][tid]);
        top2_merge(m, s_red[2][tid]);
        top2_merge(m, s_red[3][tid]);
        g_part[(size_t)(rowStart + tid) * NSPLIT + split] = m;
    }
}

// ---------------------------------------------------------------------------
// Kernel 3: merge splits, compute losses/gates, final scalar
// ---------------------------------------------------------------------------
__global__ void __launch_bounds__(256) loss_kernel(float* __restrict__ out) {
    const int t = threadIdx.x;
    float sum_lg = 0.0f, sum_g = 0.0f;

    for (int r = t; r < NB; r += 256) {
        float2 m = g_part[(size_t)r * NSPLIT + 0];
        #pragma unroll
        for (int p = 1; p < NSPLIT; p++) top2_merge(m, g_part[(size_t)r * NSPLIT + p]);
        float d2[2] = {m.x, m.y};
        #pragma unroll
        for (int e = 0; e < 2; e++) {
            float dist = sqrtf(fmaxf(2.0f - 2.0f * d2[e], 0.0f));
            float loss = -logf(dist + 1e-8f);
            float g    = 1.0f / (1.0f + expf(-(loss - 0.5f) * 10.0f));
            sum_lg += loss * g;
            sum_g  += g;
        }
    }
    #pragma unroll
    for (int o = 16; o > 0; o >>= 1) {
        sum_lg += __shfl_xor_sync(0xFFFFFFFFu, sum_lg, o);
        sum_g  += __shfl_xor_sync(0xFFFFFFFFu, sum_g,  o);
    }
    __shared__ float s_lg[8], s_g[8];
    int lane = t & 31, w = t >> 5;
    if (lane == 0) { s_lg[w] = sum_lg; s_g[w] = sum_g; }
    __syncthreads();
    if (t == 0) {
        float tl = 0.0f, tg = 0.0f;
        #pragma unroll
        for (int i = 0; i < 8; i++) { tl += s_lg[i]; tg += s_g[i]; }
        float weighted_mean = tl / (float)(NB * 2);
        float gated_mean    = tl / fmaxf(tg, 1.0f);
        out[0] = 0.5f * weighted_mean + 0.5f * gated_mean;
    }
}

// ---------------------------------------------------------------------------
extern "C" void kernel_launch(void* const* d_in, const int* in_sizes, int n_in,
                              void* d_out, int out_size) {
    const float* x = (const float*)d_in[0];
    float* out = (float*)d_out;

    normalize_kernel<<<NB, 256>>>(x);
    top2_mma_kernel<<<dim3(NB / BM, NSPLIT), THREADS>>>();
    loss_kernel<<<1, 256>>>(out);
}

// round 4
// speedup vs baseline: 6.5510x; 1.0134x over previous
#include <cuda_runtime.h>
#include <cuda_fp16.h>
#include <cstdint>
#include <math.h>

#define NB 8192
#define ND 1024
#define BM 128
#define BN 128
#define BK 32
#define NBLK (NB / BM)              /* 64 row/col blocks */
#define NTILES (NBLK * (NBLK + 1) / 2)  /* 2080 upper-tri tiles */
#define THREADS 256
#define LDS_PAD 40                  /* halves per smem row (80B stride) */
#define KBLOCKS (ND / BK)           /* 32 */

// ---------------- static device scratch (no allocation) --------------------
__device__ __half g_h[NB * ND];             // normalized rows fp16 (16 MB)
__device__ float2 g_part[NB * NBLK];        // per-(row, colblock) top-2 (4 MB)

// ---------------- PTX helpers ----------------------------------------------
__device__ __forceinline__ uint32_t smem_u32(const void* p) {
    uint32_t a;
    asm("{ .reg .u64 t; cvta.to.shared.u64 t, %1; cvt.u32.u64 %0, t; }" : "=r"(a) : "l"(p));
    return a;
}
#define CP_ASYNC16(sm, gp) \
    asm volatile("cp.async.cg.shared.global [%0], [%1], 16;" :: "r"(sm), "l"(gp))
#define CP_COMMIT() asm volatile("cp.async.commit_group;" ::: "memory")
#define CP_WAIT1()  asm volatile("cp.async.wait_group 1;" ::: "memory")
#define CP_WAIT0()  asm volatile("cp.async.wait_group 0;" ::: "memory")
#define LDMATRIX_X4(r0, r1, r2, r3, addr) \
    asm volatile("ldmatrix.sync.aligned.m8n8.x4.shared.b16 {%0,%1,%2,%3}, [%4];" \
                 : "=r"(r0), "=r"(r1), "=r"(r2), "=r"(r3) : "r"(addr))
#define MMA16816(c, a, b0, b1) \
    asm volatile("mma.sync.aligned.m16n8k16.row.col.f32.f16.f16.f32 " \
                 "{%0,%1,%2,%3},{%4,%5,%6,%7},{%8,%9},{%0,%1,%2,%3};" \
                 : "+f"((c)[0]), "+f"((c)[1]), "+f"((c)[2]), "+f"((c)[3]) \
                 : "r"((a)[0]), "r"((a)[1]), "r"((a)[2]), "r"((a)[3]), "r"(b0), "r"(b1))

__device__ __forceinline__ void top2_merge(float2& t, float2 q) {
    if (q.x > t.x) { t.y = fmaxf(t.x, q.y); t.x = q.x; }
    else           { t.y = fmaxf(t.y, q.x); }
}
__device__ __forceinline__ void top2_push(float2& t, float v) {
    if (v > t.x) { t.y = t.x; t.x = v; }
    else if (v > t.y) { t.y = v; }
}
__device__ __forceinline__ void top2_shfl_merge(float2& t, int off) {
    float2 q;
    q.x = __shfl_xor_sync(0xFFFFFFFFu, t.x, off);
    q.y = __shfl_xor_sync(0xFFFFFFFFu, t.y, off);
    top2_merge(t, q);
}

// ---------------------------------------------------------------------------
// Kernel 1: L2-normalize rows, store fp16
// ---------------------------------------------------------------------------
__global__ void __launch_bounds__(256) normalize_kernel(const float* __restrict__ x) {
    int row = blockIdx.x;
    int t = threadIdx.x;
    const float4* xr = reinterpret_cast<const float4*>(x + (size_t)row * ND);
    float4 v = xr[t];
    float s = v.x * v.x + v.y * v.y + v.z * v.z + v.w * v.w;
    #pragma unroll
    for (int o = 16; o > 0; o >>= 1) s += __shfl_xor_sync(0xFFFFFFFFu, s, o);
    __shared__ float ws[8];
    int lane = t & 31, w = t >> 5;
    if (lane == 0) ws[w] = s;
    __syncthreads();
    if (t < 8) {
        float q = ws[t];
        #pragma unroll
        for (int o = 4; o > 0; o >>= 1) q += __shfl_xor_sync(0x000000FFu, q, o);
        if (t == 0) ws[0] = q;
    }
    __syncthreads();
    float inv = 1.0f / fmaxf(sqrtf(ws[0]), 1e-8f);
    __half2* oh = reinterpret_cast<__half2*>(g_h + (size_t)row * ND);
    oh[t * 2 + 0] = __floats2half2_rn(v.x * inv, v.y * inv);
    oh[t * 2 + 1] = __floats2half2_rn(v.z * inv, v.w * inv);
}

// ---------------------------------------------------------------------------
// Kernel 2: symmetric fp16 mma.sync — one upper-triangle 128x128 tile per CTA,
//           row-side AND column-side top-2 reductions.
// ---------------------------------------------------------------------------
__global__ void __launch_bounds__(THREADS) top2_sym_kernel() {
    __shared__ __half sA[2][BM * LDS_PAD];
    __shared__ __half sB[2][BN * LDS_PAD];
    __shared__ float2 s_redr[4][BM];   // row-side partials per N-warp
    __shared__ float2 s_redc[2][BN];   // col-side partials per M-warp

    // decode upper-triangle (i, j), i <= j
    int i = 0, base = 0;
    {
        const int idx = blockIdx.x;
        while (base + (NBLK - i) <= idx) { base += NBLK - i; ++i; }
        base = idx - base;
    }
    const int j = i + base;
    const int rowStart = i * BM;
    const int colStart = j * BN;

    const int tid = threadIdx.x;
    const int wid = tid >> 5, lane = tid & 31;
    const int warpM = wid >> 2, warpN = wid & 3;   // 2 x 4 warp grid

    const uint32_t sAu = smem_u32(&sA[0][0]);
    const uint32_t sBu = smem_u32(&sB[0][0]);
    const uint32_t BUFB = BM * LDS_PAD * 2;

    const int a_r = lane & 15;
    const int a_k = (lane >> 4) << 3;
    const int b_n = (lane & 7) + ((lane >> 4) << 3);
    const int b_k = ((lane >> 3) & 1) << 3;

    const int l_r0 = tid >> 2, l_k0 = tid & 3;
    const int l_r1 = (tid + 256) >> 2, l_k1 = (tid + 256) & 3;

    float acc[4][4][4];
    #pragma unroll
    for (int mi = 0; mi < 4; mi++)
        #pragma unroll
        for (int nj = 0; nj < 4; nj++)
            #pragma unroll
            for (int e = 0; e < 4; e++) acc[mi][nj][e] = 0.0f;

    // ---- prologue: stage 0 ----
    CP_ASYNC16(sAu + (l_r0 * LDS_PAD + l_k0 * 8) * 2,
               g_h + (size_t)(rowStart + l_r0) * ND + l_k0 * 8);
    CP_ASYNC16(sAu + (l_r1 * LDS_PAD + l_k1 * 8) * 2,
               g_h + (size_t)(rowStart + l_r1) * ND + l_k1 * 8);
    CP_ASYNC16(sBu + (l_r0 * LDS_PAD + l_k0 * 8) * 2,
               g_h + (size_t)(colStart + l_r0) * ND + l_k0 * 8);
    CP_ASYNC16(sBu + (l_r1 * LDS_PAD + l_k1 * 8) * 2,
               g_h + (size_t)(colStart + l_r1) * ND + l_k1 * 8);
    CP_COMMIT();

    for (int kb = 0; kb < KBLOCKS; kb++) {
        if (kb + 1 < KBLOCKS) {
            const int k0 = (kb + 1) * BK;
            const uint32_t bo = ((kb + 1) & 1) * BUFB;
            CP_ASYNC16(sAu + bo + (l_r0 * LDS_PAD + l_k0 * 8) * 2,
                       g_h + (size_t)(rowStart + l_r0) * ND + k0 + l_k0 * 8);
            CP_ASYNC16(sAu + bo + (l_r1 * LDS_PAD + l_k1 * 8) * 2,
                       g_h + (size_t)(rowStart + l_r1) * ND + k0 + l_k1 * 8);
            CP_ASYNC16(sBu + bo + (l_r0 * LDS_PAD + l_k0 * 8) * 2,
                       g_h + (size_t)(colStart + l_r0) * ND + k0 + l_k0 * 8);
            CP_ASYNC16(sBu + bo + (l_r1 * LDS_PAD + l_k1 * 8) * 2,
                       g_h + (size_t)(colStart + l_r1) * ND + k0 + l_k1 * 8);
            CP_COMMIT();
            CP_WAIT1();
        } else {
            CP_WAIT0();
        }
        __syncthreads();

        const uint32_t bo = (kb & 1) * BUFB;
        #pragma unroll
        for (int ks = 0; ks < 2; ks++) {
            uint32_t af[4][4];
            #pragma unroll
            for (int mi = 0; mi < 4; mi++) {
                uint32_t addr = sAu + bo +
                    ((warpM * 64 + mi * 16 + a_r) * LDS_PAD + ks * 16 + a_k) * 2;
                LDMATRIX_X4(af[mi][0], af[mi][1], af[mi][2], af[mi][3], addr);
            }
            uint32_t bf[2][4];
            #pragma unroll
            for (int nb = 0; nb < 2; nb++) {
                uint32_t addr = sBu + bo +
                    ((warpN * 32 + nb * 16 + b_n) * LDS_PAD + ks * 16 + b_k) * 2;
                LDMATRIX_X4(bf[nb][0], bf[nb][1], bf[nb][2], bf[nb][3], addr);
            }
            #pragma unroll
            for (int mi = 0; mi < 4; mi++)
                #pragma unroll
                for (int nj = 0; nj < 4; nj++)
                    MMA16816(acc[mi][nj], af[mi],
                             bf[nj >> 1][(nj & 1) * 2], bf[nj >> 1][(nj & 1) * 2 + 1]);
        }
        __syncthreads();
    }

    // ================= epilogue =================
    // mask diagonal (only possible when i == j; compare is cheap, keep unconditional)
    // row-side running top-2 (8 per thread) + col-side running top-2 (8 per thread)
    float2 run[8];
    float2 crun[4][2];
    #pragma unroll
    for (int t2 = 0; t2 < 8; t2++) run[t2] = make_float2(-2.0f, -2.0f);
    #pragma unroll
    for (int nj = 0; nj < 4; nj++) {
        crun[nj][0] = make_float2(-2.0f, -2.0f);
        crun[nj][1] = make_float2(-2.0f, -2.0f);
    }

    #pragma unroll
    for (int mi = 0; mi < 4; mi++) {
        const int row0 = rowStart + warpM * 64 + mi * 16 + (lane >> 2);
        #pragma unroll
        for (int nj = 0; nj < 4; nj++) {
            const int col0 = colStart + warpN * 32 + nj * 8 + (lane & 3) * 2;
            float c0 = acc[mi][nj][0], c1 = acc[mi][nj][1];
            float c2 = acc[mi][nj][2], c3 = acc[mi][nj][3];
            if (col0     == row0)     c0 = -2.0f;
            if (col0 + 1 == row0)     c1 = -2.0f;
            if (col0     == row0 + 8) c2 = -2.0f;
            if (col0 + 1 == row0 + 8) c3 = -2.0f;
            top2_push(run[mi * 2 + 0], c0);
            top2_push(run[mi * 2 + 0], c1);
            top2_push(run[mi * 2 + 1], c2);
            top2_push(run[mi * 2 + 1], c3);
            top2_push(crun[nj][0], c0);
            top2_push(crun[nj][1], c1);
            top2_push(crun[nj][0], c2);
            top2_push(crun[nj][1], c3);
        }
    }

    // ---- row-side: merge across lane quads (cols), stash per N-warp ----
    #pragma unroll
    for (int t2 = 0; t2 < 8; t2++) {
        top2_shfl_merge(run[t2], 1);
        top2_shfl_merge(run[t2], 2);
    }
    if ((lane & 3) == 0) {
        #pragma unroll
        for (int mi = 0; mi < 4; mi++) {
            int rbase = warpM * 64 + mi * 16 + (lane >> 2);
            s_redr[warpN][rbase]     = run[mi * 2 + 0];
            s_redr[warpN][rbase + 8] = run[mi * 2 + 1];
        }
    }

    // ---- col-side: merge across row lanes (lane>>2 axis), stash per M-warp ----
    if (i != j) {
        #pragma unroll
        for (int nj = 0; nj < 4; nj++) {
            #pragma unroll
            for (int h = 0; h < 2; h++) {
                top2_shfl_merge(crun[nj][h], 4);
                top2_shfl_merge(crun[nj][h], 8);
                top2_shfl_merge(crun[nj][h], 16);
            }
        }
        if (lane < 4) {
            #pragma unroll
            for (int nj = 0; nj < 4; nj++) {
                int cbase = warpN * 32 + nj * 8 + lane * 2;
                s_redc[warpM][cbase]     = crun[nj][0];
                s_redc[warpM][cbase + 1] = crun[nj][1];
            }
        }
    }
    __syncthreads();

    if (tid < BM) {
        float2 m = s_redr[0][tid];
        top2_merge(m, s_redr[1][tid]);
        top2_merge(m, s_redr[2][tid]);
        top2_merge(m, s_redr[3][tid]);
        g_part[(size_t)(rowStart + tid) * NBLK + j] = m;
    }
    if (i != j && tid >= 128 && tid < 128 + BN) {
        int c = tid - 128;
        float2 m = s_redc[0][c];
        top2_merge(m, s_redc[1][c]);
        g_part[(size_t)(colStart + c) * NBLK + i] = m;
    }
}

// ---------------------------------------------------------------------------
// Kernel 3: merge 64 partials per row, compute losses/gates, final scalar
// ---------------------------------------------------------------------------
__global__ void __launch_bounds__(256) loss_kernel(float* __restrict__ out) {
    const int t = threadIdx.x;
    float sum_lg = 0.0f, sum_g = 0.0f;

    for (int r = t; r < NB; r += 256) {
        const float2* p = g_part + (size_t)r * NBLK;
        float2 m = p[0];
        #pragma unroll 8
        for (int b = 1; b < NBLK; b++) top2_merge(m, p[b]);
        float d2[2] = {m.x, m.y};
        #pragma unroll
        for (int e = 0; e < 2; e++) {
            float dist = sqrtf(fmaxf(2.0f - 2.0f * d2[e], 0.0f));
            float loss = -logf(dist + 1e-8f);
            float g    = 1.0f / (1.0f + expf(-(loss - 0.5f) * 10.0f));
            sum_lg += loss * g;
            sum_g  += g;
        }
    }
    #pragma unroll
    for (int o = 16; o > 0; o >>= 1) {
        sum_lg += __shfl_xor_sync(0xFFFFFFFFu, sum_lg, o);
        sum_g  += __shfl_xor_sync(0xFFFFFFFFu, sum_g,  o);
    }
    __shared__ float s_lg[8], s_g[8];
    int lane = t & 31, w = t >> 5;
    if (lane == 0) { s_lg[w] = sum_lg; s_g[w] = sum_g; }
    __syncthreads();
    if (t == 0) {
        float tl = 0.0f, tg = 0.0f;
        #pragma unroll
        for (int q = 0; q < 8; q++) { tl += s_lg[q]; tg += s_g[q]; }
        float weighted_mean = tl / (float)(NB * 2);
        float gated_mean    = tl / fmaxf(tg, 1.0f);
        out[0] = 0.5f * weighted_mean + 0.5f * gated_mean;
    }
}

// ---------------------------------------------------------------------------
extern "C" void kernel_launch(void* const* d_in, const int* in_sizes, int n_in,
                              void* d_out, int out_size) {
    const float* x = (const float*)d_in[0];
    float* out = (float*)d_out;

    normalize_kernel<<<NB, 256>>>(x);
    top2_sym_kernel<<<NTILES, THREADS>>>();
    loss_kernel<<<1, 256>>>(out);
}